// round 1
// baseline (speedup 1.0000x reference)
#include <cuda_runtime.h>
#include <math.h>

// Problem dimensions (fixed)
#define B_   128
#define T_   32
#define DIN  1024
#define H_   1024
#define V_   2048
#define A_   512
#define NROI 64

// ---------------- scratch (static device globals; no allocations) ----------
__device__ float g_mean[B_ * V_];              // mean visual     [128,2048]
__device__ float g_h[B_ * H_];                 // hidden state    [128,1024]
__device__ float g_c[B_ * H_];                 // cell state      [128,1024]
__device__ float g_va[(size_t)B_ * NROI * A_]; // visual attn enc [128,64,512]
__device__ float g_pi[(size_t)B_ * T_ * 6 * H_]; // x projections [128,32,6144] (~100MB)
__device__ float g_he[B_ * A_];                // h attn enc      [128,512]
__device__ float g_ctx[B_ * V_];               // context         [128,2048]
__device__ float g_ps[B_ * 5 * H_];            // state proj      [128,5120]
__device__ float g_pa[B_ * 5 * H_];            // attn proj       [128,5120]

__device__ __forceinline__ float sigmoidf(float x) { return 1.0f / (1.0f + expf(-x)); }

// ---------------------------------------------------------------------------
// mean_vis[b,v] = sum_{n<L} visual[b,n,v] / L
// ---------------------------------------------------------------------------
__global__ void mean_vis_kernel(const float* __restrict__ visual,
                                const int* __restrict__ ls_rois)
{
    int b = blockIdx.x;
    int L = ls_rois[b];
    const float* vb = visual + (size_t)b * NROI * V_;
    float invL = 1.0f / (float)L;
    for (int v = threadIdx.x; v < V_; v += blockDim.x) {
        float s = 0.0f;
        for (int n = 0; n < L; n++) s += vb[(size_t)n * V_ + v];
        g_mean[b * V_ + v] = s * invL;
    }
}

// ---------------------------------------------------------------------------
// Generic NT GEMM with bias: C[m,n] = sum_k A[m,k]*W[n,k] + bias[n]
// BM=BN=64, BK=16, 256 threads, 4x4 per thread. Requires M%64==0, N%64==0, K%16==0.
// ---------------------------------------------------------------------------
__global__ __launch_bounds__(256)
void gemm_nt_bias(const float* __restrict__ A, const float* __restrict__ W,
                  const float* __restrict__ bias, float* __restrict__ C,
                  int M, int N, int K)
{
    __shared__ float As[16][64];
    __shared__ float Bs[16][64];

    const int bm = blockIdx.y * 64;
    const int bn = blockIdx.x * 64;
    const int tid = threadIdx.x;
    const int tr = tid >> 4;            // 0..15 (row group)
    const int tc = tid & 15;            // 0..15 (col group)
    const int lr = tid >> 2;            // 0..63 (load row)
    const int lc = (tid & 3) << 2;      // 0,4,8,12 (load col base)

    const float* Ap = A + (size_t)(bm + lr) * K + lc;
    const float* Wp = W + (size_t)(bn + lr) * K + lc;

    float acc[4][4];
#pragma unroll
    for (int i = 0; i < 4; i++)
#pragma unroll
        for (int j = 0; j < 4; j++) acc[i][j] = 0.0f;

    for (int k0 = 0; k0 < K; k0 += 16) {
        float4 av = *(const float4*)(Ap + k0);
        float4 wv = *(const float4*)(Wp + k0);
        As[lc + 0][lr] = av.x; As[lc + 1][lr] = av.y;
        As[lc + 2][lr] = av.z; As[lc + 3][lr] = av.w;
        Bs[lc + 0][lr] = wv.x; Bs[lc + 1][lr] = wv.y;
        Bs[lc + 2][lr] = wv.z; Bs[lc + 3][lr] = wv.w;
        __syncthreads();
#pragma unroll
        for (int kk = 0; kk < 16; kk++) {
            float4 a = *(const float4*)&As[kk][tr << 2];
            float4 w = *(const float4*)&Bs[kk][tc << 2];
            acc[0][0] += a.x * w.x; acc[0][1] += a.x * w.y; acc[0][2] += a.x * w.z; acc[0][3] += a.x * w.w;
            acc[1][0] += a.y * w.x; acc[1][1] += a.y * w.y; acc[1][2] += a.y * w.z; acc[1][3] += a.y * w.w;
            acc[2][0] += a.z * w.x; acc[2][1] += a.z * w.y; acc[2][2] += a.z * w.z; acc[2][3] += a.z * w.w;
            acc[3][0] += a.w * w.x; acc[3][1] += a.w * w.y; acc[3][2] += a.w * w.z; acc[3][3] += a.w * w.w;
        }
        __syncthreads();
    }

    float4 bv4 = *(const float4*)(bias + bn + (tc << 2));
#pragma unroll
    for (int i = 0; i < 4; i++) {
        float4 o;
        o.x = acc[i][0] + bv4.x;
        o.y = acc[i][1] + bv4.y;
        o.z = acc[i][2] + bv4.z;
        o.w = acc[i][3] + bv4.w;
        *(float4*)(C + (size_t)(bm + (tr << 2) + i) * N + bn + (tc << 2)) = o;
    }
}

// ---------------------------------------------------------------------------
// Attention step: logits_n = Wp . relu(va[b,n,:] + he[b,:]) + bp,
// masked softmax over n<L, ctx[b,:] = sum_n att[n]*visual[b,n,:]
// One block per batch element, 256 threads (8 warps).
// ---------------------------------------------------------------------------
__global__ __launch_bounds__(256)
void attn_kernel(const float* __restrict__ visual,
                 const float* __restrict__ Wp, const float* __restrict__ bp,
                 const int* __restrict__ ls_rois)
{
    int b = blockIdx.x;
    int tid = threadIdx.x;
    int warp = tid >> 5, lane = tid & 31;

    __shared__ float he_s[A_];
    __shared__ float wp_s[A_];
    __shared__ float att[NROI];

    for (int a = tid; a < A_; a += 256) {
        he_s[a] = g_he[b * A_ + a];
        wp_s[a] = Wp[a];
    }
    __syncthreads();

    int L = ls_rois[b];

    // logits: each warp handles n = warp, warp+8, ...
    for (int n = warp; n < NROI; n += 8) {
        float s = 0.0f;
        if (n < L) {
            const float* vrow = g_va + ((size_t)b * NROI + n) * A_;
            for (int a = lane; a < A_; a += 32) {
                float t = vrow[a] + he_s[a];
                s += wp_s[a] * fmaxf(t, 0.0f);
            }
        }
#pragma unroll
        for (int o = 16; o; o >>= 1) s += __shfl_xor_sync(0xffffffffu, s, o);
        if (lane == 0) att[n] = s + bp[0];
    }
    __syncthreads();

    // softmax over n<L (serial by thread 0: only 64 elems, negligible)
    if (tid == 0) {
        float mx = -3.0e38f;
        for (int n = 0; n < L; n++) mx = fmaxf(mx, att[n]);
        float den = 0.0f;
        for (int n = 0; n < L; n++) { float e = expf(att[n] - mx); att[n] = e; den += e; }
        float inv = 1.0f / den;
        for (int n = 0; n < L; n++) att[n] *= inv;
        for (int n = L; n < NROI; n++) att[n] = 0.0f;
    }
    __syncthreads();

    const float* vb = visual + (size_t)b * NROI * V_;
    for (int v = tid; v < V_; v += 256) {
        float s = 0.0f;
        for (int n = 0; n < L; n++) s += att[n] * vb[(size_t)n * V_ + v];
        g_ctx[b * V_ + v] = s;
    }
}

// ---------------------------------------------------------------------------
// LSTM gates + highway + state update + output projection for step t.
// One block per batch element, 256 threads.
// ---------------------------------------------------------------------------
__global__ __launch_bounds__(256)
void gate_kernel(const float* __restrict__ Wo, const float* __restrict__ bo,
                 const int* __restrict__ seq_lens, float* __restrict__ y, int t)
{
    int b = blockIdx.x;
    int tid = threadIdx.x;
    bool valid = (t < seq_lens[b]);

    const float* pi = g_pi + ((size_t)b * T_ + t) * (6 * H_);
    const float* ps = g_ps + (size_t)b * (5 * H_);
    const float* pa = g_pa + (size_t)b * (5 * H_);

    float part = 0.0f;
    for (int j = tid; j < H_; j += 256) {
        float ig = sigmoidf(pi[j]          + ps[j]          + pa[j]);
        float fg = sigmoidf(pi[H_ + j]     + ps[H_ + j]     + pa[H_ + j]);
        float mi = tanhf   (pi[2 * H_ + j] + ps[2 * H_ + j] + pa[2 * H_ + j]);
        float og = sigmoidf(pi[3 * H_ + j] + ps[3 * H_ + j] + pa[3 * H_ + j]);
        float mem = ig * mi + fg * g_c[b * H_ + j];
        float out = og * tanhf(mem);
        float hw = sigmoidf(pi[4 * H_ + j] + ps[4 * H_ + j] + pa[4 * H_ + j]);
        out = hw * out + (1.0f - hw) * pi[5 * H_ + j];
        part += out * Wo[j];
        if (valid) {
            g_h[b * H_ + j] = out;
            g_c[b * H_ + j] = mem;
        }
    }

    __shared__ float red[256];
    red[tid] = part;
    __syncthreads();
    for (int s = 128; s; s >>= 1) {
        if (tid < s) red[tid] += red[tid + s];
        __syncthreads();
    }
    if (tid == 0) y[b * T_ + t] = valid ? (red[0] + bo[0]) : 0.0f;
}

// ---------------------------------------------------------------------------
extern "C" void kernel_launch(void* const* d_in, const int* in_sizes, int n_in,
                              void* d_out, int out_size)
{
    const float* x      = (const float*)d_in[0];
    const float* visual = (const float*)d_in[1];
    const float* Wi     = (const float*)d_in[2];
    const float* bi     = (const float*)d_in[3];
    const float* Ws     = (const float*)d_in[4];
    const float* bs     = (const float*)d_in[5];
    const float* Wa     = (const float*)d_in[6];
    const float* ba     = (const float*)d_in[7];
    const float* Wv     = (const float*)d_in[8];
    const float* bv     = (const float*)d_in[9];
    const float* Wh     = (const float*)d_in[10];
    const float* bh     = (const float*)d_in[11];
    const float* Wp     = (const float*)d_in[12];
    const float* bp     = (const float*)d_in[13];
    const float* W0h    = (const float*)d_in[14];
    const float* b0h    = (const float*)d_in[15];
    const float* W0c    = (const float*)d_in[16];
    const float* b0c    = (const float*)d_in[17];
    const float* Wo     = (const float*)d_in[18];
    const float* bo     = (const float*)d_in[19];
    const int* ls_rois  = (const int*)d_in[20];
    const int* seq_lens = (const int*)d_in[21];
    float* y = (float*)d_out;

    float *p_mean, *p_h, *p_c, *p_va, *p_pi, *p_he, *p_ctx, *p_ps, *p_pa;
    cudaGetSymbolAddress((void**)&p_mean, g_mean);
    cudaGetSymbolAddress((void**)&p_h,    g_h);
    cudaGetSymbolAddress((void**)&p_c,    g_c);
    cudaGetSymbolAddress((void**)&p_va,   g_va);
    cudaGetSymbolAddress((void**)&p_pi,   g_pi);
    cudaGetSymbolAddress((void**)&p_he,   g_he);
    cudaGetSymbolAddress((void**)&p_ctx,  g_ctx);
    cudaGetSymbolAddress((void**)&p_ps,   g_ps);
    cudaGetSymbolAddress((void**)&p_pa,   g_pa);

    // ---- loop-invariant precompute ----
    mean_vis_kernel<<<B_, 256>>>(visual, ls_rois);

    // h0 = mean_vis @ W0h^T + b0h ; c0 = mean_vis @ W0c^T + b0c
    gemm_nt_bias<<<dim3(H_ / 64, B_ / 64), 256>>>(p_mean, W0h, b0h, p_h, B_, H_, V_);
    gemm_nt_bias<<<dim3(H_ / 64, B_ / 64), 256>>>(p_mean, W0c, b0c, p_c, B_, H_, V_);

    // va = visual @ Wv^T + bv   (flattened [B*N, V] x [A, V]^T)
    gemm_nt_bias<<<dim3(A_ / 64, (B_ * NROI) / 64), 256>>>(visual, Wv, bv, p_va,
                                                           B_ * NROI, A_, V_);

    // pi = x @ Wi^T + bi for ALL timesteps  ([B*T, DIN] x [6H, DIN]^T)
    gemm_nt_bias<<<dim3((6 * H_) / 64, (B_ * T_) / 64), 256>>>(x, Wi, bi, p_pi,
                                                               B_ * T_, 6 * H_, DIN);

    // ---- recurrent steps ----
    for (int t = 0; t < T_; t++) {
        // he = h @ Wh^T + bh
        gemm_nt_bias<<<dim3(A_ / 64, B_ / 64), 256>>>(p_h, Wh, bh, p_he, B_, A_, H_);
        // attention -> ctx
        attn_kernel<<<B_, 256>>>(visual, Wp, bp, ls_rois);
        // ps = h @ Ws^T + bs
        gemm_nt_bias<<<dim3((5 * H_) / 64, B_ / 64), 256>>>(p_h, Ws, bs, p_ps, B_, 5 * H_, H_);
        // pa = ctx @ Wa^T + ba
        gemm_nt_bias<<<dim3((5 * H_) / 64, B_ / 64), 256>>>(p_ctx, Wa, ba, p_pa, B_, 5 * H_, V_);
        // gates + state update + y
        gate_kernel<<<B_, 256>>>(Wo, bo, seq_lens, y, t);
    }
}

// round 2
// speedup vs baseline: 1.0323x; 1.0323x over previous
#include <cuda_runtime.h>
#include <math.h>

// Problem dimensions (fixed)
#define B_   128
#define T_   32
#define DIN  1024
#define H_   1024
#define V_   2048
#define A_   512
#define NROI 64

// ---------------- scratch (static device globals; no allocations) ----------
__device__ float g_mean[B_ * V_];                // mean visual     [128,2048]
__device__ float g_h[B_ * H_];                   // hidden state    [128,1024]
__device__ float g_c[B_ * H_];                   // cell state      [128,1024]
__device__ float g_va[(size_t)B_ * NROI * A_];   // visual attn enc [128,64,512]
__device__ float g_pi[(size_t)B_ * T_ * 6 * H_]; // x projections   [128,32,6144]
__device__ float g_he[B_ * A_];                  // h attn enc      [128,512]
__device__ float g_ctx[B_ * V_];                 // context         [128,2048]
__device__ float g_ps[B_ * 5 * H_];              // state proj      [128,5120]
__device__ float g_pa[B_ * 5 * H_];              // attn proj       [128,5120]

__device__ __forceinline__ float sigmoidf(float x) { return 1.0f / (1.0f + expf(-x)); }

// ---------------------------------------------------------------------------
// mean_vis[b,v] = sum_{n<L} visual[b,n,v] / L
// ---------------------------------------------------------------------------
__global__ void mean_vis_kernel(const float* __restrict__ visual,
                                const int* __restrict__ ls_rois)
{
    int b = blockIdx.x;
    int L = ls_rois[b];
    const float* vb = visual + (size_t)b * NROI * V_;
    float invL = 1.0f / (float)L;
    for (int v = threadIdx.x; v < V_; v += blockDim.x) {
        float s = 0.0f;
        for (int n = 0; n < L; n++) s += vb[(size_t)n * V_ + v];
        g_mean[b * V_ + v] = s * invL;
    }
}

// ---------------------------------------------------------------------------
// Generic NT GEMM with bias (precompute path): C[m,n] = sum_k A[m,k]*W[n,k] + b[n]
// BM=BN=64, BK=16, 256 threads, 4x4 per thread. (measured ~87% of fp32 peak)
// ---------------------------------------------------------------------------
__global__ __launch_bounds__(256)
void gemm_nt_bias(const float* __restrict__ A, const float* __restrict__ W,
                  const float* __restrict__ bias, float* __restrict__ C,
                  int M, int N, int K)
{
    __shared__ float As[16][64];
    __shared__ float Bs[16][64];

    const int bm = blockIdx.y * 64;
    const int bn = blockIdx.x * 64;
    const int tid = threadIdx.x;
    const int tr = tid >> 4;
    const int tc = tid & 15;
    const int lr = tid >> 2;
    const int lc = (tid & 3) << 2;

    const float* Ap = A + (size_t)(bm + lr) * K + lc;
    const float* Wp = W + (size_t)(bn + lr) * K + lc;

    float acc[4][4];
#pragma unroll
    for (int i = 0; i < 4; i++)
#pragma unroll
        for (int j = 0; j < 4; j++) acc[i][j] = 0.0f;

    for (int k0 = 0; k0 < K; k0 += 16) {
        float4 av = *(const float4*)(Ap + k0);
        float4 wv = *(const float4*)(Wp + k0);
        As[lc + 0][lr] = av.x; As[lc + 1][lr] = av.y;
        As[lc + 2][lr] = av.z; As[lc + 3][lr] = av.w;
        Bs[lc + 0][lr] = wv.x; Bs[lc + 1][lr] = wv.y;
        Bs[lc + 2][lr] = wv.z; Bs[lc + 3][lr] = wv.w;
        __syncthreads();
#pragma unroll
        for (int kk = 0; kk < 16; kk++) {
            float4 a = *(const float4*)&As[kk][tr << 2];
            float4 w = *(const float4*)&Bs[kk][tc << 2];
            acc[0][0] += a.x * w.x; acc[0][1] += a.x * w.y; acc[0][2] += a.x * w.z; acc[0][3] += a.x * w.w;
            acc[1][0] += a.y * w.x; acc[1][1] += a.y * w.y; acc[1][2] += a.y * w.z; acc[1][3] += a.y * w.w;
            acc[2][0] += a.z * w.x; acc[2][1] += a.z * w.y; acc[2][2] += a.z * w.z; acc[2][3] += a.z * w.w;
            acc[3][0] += a.w * w.x; acc[3][1] += a.w * w.y; acc[3][2] += a.w * w.z; acc[3][3] += a.w * w.w;
        }
        __syncthreads();
    }

    float4 bv4 = *(const float4*)(bias + bn + (tc << 2));
#pragma unroll
    for (int i = 0; i < 4; i++) {
        float4 o;
        o.x = acc[i][0] + bv4.x;
        o.y = acc[i][1] + bv4.y;
        o.z = acc[i][2] + bv4.z;
        o.w = acc[i][3] + bv4.w;
        *(float4*)(C + (size_t)(bm + (tr << 2) + i) * N + bn + (tc << 2)) = o;
    }
}

// ---------------------------------------------------------------------------
// M=128-specialized GEMM core. One block computes C[0:128, n0:n0+32] where
// the caller passes W/bias/C already offset to column n0. BK=16, 256 threads,
// 4x4 microtile (thread grid 32 rows x 8 cols). fma:smem = 16 FMA : 32B
// (balanced against 128B/cyc smem vs 64 FMA-lane/cyc).
// ---------------------------------------------------------------------------
__device__ __forceinline__
void gemm_m128_core(float As[16][128], float Bs[16][32],
                    const float* __restrict__ A, const float* __restrict__ Wn,
                    const float* __restrict__ biasn, float* __restrict__ Cn,
                    int ldc, int K)
{
    const int tid = threadIdx.x;
    const int lm  = tid & 127;            // A-load row
    const int lkh = (tid >> 7) << 3;      // A-load k base: 0 or 8
    const int bn  = tid >> 2;             // W-load row (tid<128 -> 0..31)
    const int bk  = (tid & 3) << 2;       // W-load k base
    const int ty  = tid >> 3;             // 0..31  (4 rows each)
    const int tx  = tid & 7;              // 0..7   (4 cols each)

    const float* Ap = A + (size_t)lm * K + lkh;
    const float* Wp = Wn + (size_t)bn * K + bk;

    float acc[4][4];
#pragma unroll
    for (int i = 0; i < 4; i++)
#pragma unroll
        for (int j = 0; j < 4; j++) acc[i][j] = 0.0f;

    for (int k0 = 0; k0 < K; k0 += 16) {
        float4 a0 = *(const float4*)(Ap + k0);
        float4 a1 = *(const float4*)(Ap + k0 + 4);
        As[lkh + 0][lm] = a0.x; As[lkh + 1][lm] = a0.y;
        As[lkh + 2][lm] = a0.z; As[lkh + 3][lm] = a0.w;
        As[lkh + 4][lm] = a1.x; As[lkh + 5][lm] = a1.y;
        As[lkh + 6][lm] = a1.z; As[lkh + 7][lm] = a1.w;
        if (tid < 128) {
            float4 w = *(const float4*)(Wp + k0);
            Bs[bk + 0][bn] = w.x; Bs[bk + 1][bn] = w.y;
            Bs[bk + 2][bn] = w.z; Bs[bk + 3][bn] = w.w;
        }
        __syncthreads();
#pragma unroll
        for (int kk = 0; kk < 16; kk++) {
            float4 a = *(const float4*)&As[kk][ty << 2];
            float4 b = *(const float4*)&Bs[kk][tx << 2];
            acc[0][0] += a.x * b.x; acc[0][1] += a.x * b.y; acc[0][2] += a.x * b.z; acc[0][3] += a.x * b.w;
            acc[1][0] += a.y * b.x; acc[1][1] += a.y * b.y; acc[1][2] += a.y * b.z; acc[1][3] += a.y * b.w;
            acc[2][0] += a.z * b.x; acc[2][1] += a.z * b.y; acc[2][2] += a.z * b.z; acc[2][3] += a.z * b.w;
            acc[3][0] += a.w * b.x; acc[3][1] += a.w * b.y; acc[3][2] += a.w * b.z; acc[3][3] += a.w * b.w;
        }
        __syncthreads();
    }

    float4 bv = *(const float4*)(biasn + (tx << 2));
#pragma unroll
    for (int i = 0; i < 4; i++) {
        float4 o;
        o.x = acc[i][0] + bv.x;
        o.y = acc[i][1] + bv.y;
        o.z = acc[i][2] + bv.z;
        o.w = acc[i][3] + bv.w;
        *(float4*)(Cn + (size_t)((ty << 2) + i) * ldc + (tx << 2)) = o;
    }
}

// step1: [ps | he] = h @ [Ws ; Wh]^T + [bs ; bh].  grid = (5H+A)/32 = 176 blocks.
__global__ __launch_bounds__(256)
void step1_kernel(const float* __restrict__ Ws, const float* __restrict__ bs,
                  const float* __restrict__ Wh, const float* __restrict__ bh)
{
    __shared__ float As[16][128];
    __shared__ float Bs[16][32];
    int n0 = blockIdx.x << 5;
    if (n0 < 5 * H_) {
        gemm_m128_core(As, Bs, g_h, Ws + (size_t)n0 * H_, bs + n0,
                       g_ps + n0, 5 * H_, H_);
    } else {
        int m = n0 - 5 * H_;
        gemm_m128_core(As, Bs, g_h, Wh + (size_t)m * H_, bh + m,
                       g_he + m, A_, H_);
    }
}

// step2: pa = ctx @ Wa^T + ba.  grid = 5H/32 = 160 blocks.
__global__ __launch_bounds__(256)
void step2_kernel(const float* __restrict__ Wa, const float* __restrict__ ba)
{
    __shared__ float As[16][128];
    __shared__ float Bs[16][32];
    int n0 = blockIdx.x << 5;
    gemm_m128_core(As, Bs, g_ctx, Wa + (size_t)n0 * V_, ba + n0,
                   g_pa + n0, 5 * H_, V_);
}

// ---------------------------------------------------------------------------
// Attention: logits_n = Wp . relu(va[b,n,:] + he[b,:]) + bp, masked softmax,
// ctx[b,:] = sum_n att[n]*visual[b,n,:].  One block per batch element.
// ---------------------------------------------------------------------------
__global__ __launch_bounds__(256)
void attn_kernel(const float* __restrict__ visual,
                 const float* __restrict__ Wp, const float* __restrict__ bp,
                 const int* __restrict__ ls_rois)
{
    int b = blockIdx.x;
    int tid = threadIdx.x;
    int warp = tid >> 5, lane = tid & 31;

    __shared__ float he_s[A_];
    __shared__ float wp_s[A_];
    __shared__ float att[NROI];

    for (int a = tid; a < A_; a += 256) {
        he_s[a] = g_he[b * A_ + a];
        wp_s[a] = Wp[a];
    }
    __syncthreads();

    int L = ls_rois[b];

    for (int n = warp; n < NROI; n += 8) {
        float s = 0.0f;
        if (n < L) {
            const float* vrow = g_va + ((size_t)b * NROI + n) * A_;
            for (int a = lane; a < A_; a += 32) {
                float t = vrow[a] + he_s[a];
                s += wp_s[a] * fmaxf(t, 0.0f);
            }
        }
#pragma unroll
        for (int o = 16; o; o >>= 1) s += __shfl_xor_sync(0xffffffffu, s, o);
        if (lane == 0) att[n] = s + bp[0];
    }
    __syncthreads();

    if (tid == 0) {
        float mx = -3.0e38f;
        for (int n = 0; n < L; n++) mx = fmaxf(mx, att[n]);
        float den = 0.0f;
        for (int n = 0; n < L; n++) { float e = expf(att[n] - mx); att[n] = e; den += e; }
        float inv = 1.0f / den;
        for (int n = 0; n < L; n++) att[n] *= inv;
        for (int n = L; n < NROI; n++) att[n] = 0.0f;
    }
    __syncthreads();

    const float* vb = visual + (size_t)b * NROI * V_;
    for (int v = tid; v < V_; v += 256) {
        float s = 0.0f;
        for (int n = 0; n < L; n++) s += att[n] * vb[(size_t)n * V_ + v];
        g_ctx[b * V_ + v] = s;
    }
}

// ---------------------------------------------------------------------------
// LSTM gates + highway + state update + output projection for step t.
// ---------------------------------------------------------------------------
__global__ __launch_bounds__(256)
void gate_kernel(const float* __restrict__ Wo, const float* __restrict__ bo,
                 const int* __restrict__ seq_lens, float* __restrict__ y, int t)
{
    int b = blockIdx.x;
    int tid = threadIdx.x;
    bool valid = (t < seq_lens[b]);

    const float* pi = g_pi + ((size_t)b * T_ + t) * (6 * H_);
    const float* ps = g_ps + (size_t)b * (5 * H_);
    const float* pa = g_pa + (size_t)b * (5 * H_);

    float part = 0.0f;
    for (int j = tid; j < H_; j += 256) {
        float ig = sigmoidf(pi[j]          + ps[j]          + pa[j]);
        float fg = sigmoidf(pi[H_ + j]     + ps[H_ + j]     + pa[H_ + j]);
        float mi = tanhf   (pi[2 * H_ + j] + ps[2 * H_ + j] + pa[2 * H_ + j]);
        float og = sigmoidf(pi[3 * H_ + j] + ps[3 * H_ + j] + pa[3 * H_ + j]);
        float mem = ig * mi + fg * g_c[b * H_ + j];
        float out = og * tanhf(mem);
        float hw = sigmoidf(pi[4 * H_ + j] + ps[4 * H_ + j] + pa[4 * H_ + j]);
        out = hw * out + (1.0f - hw) * pi[5 * H_ + j];
        part += out * Wo[j];
        if (valid) {
            g_h[b * H_ + j] = out;
            g_c[b * H_ + j] = mem;
        }
    }

    __shared__ float red[256];
    red[tid] = part;
    __syncthreads();
    for (int s = 128; s; s >>= 1) {
        if (tid < s) red[tid] += red[tid + s];
        __syncthreads();
    }
    if (tid == 0) y[b * T_ + t] = valid ? (red[0] + bo[0]) : 0.0f;
}

// ---------------------------------------------------------------------------
extern "C" void kernel_launch(void* const* d_in, const int* in_sizes, int n_in,
                              void* d_out, int out_size)
{
    const float* x      = (const float*)d_in[0];
    const float* visual = (const float*)d_in[1];
    const float* Wi     = (const float*)d_in[2];
    const float* bi     = (const float*)d_in[3];
    const float* Ws     = (const float*)d_in[4];
    const float* bs     = (const float*)d_in[5];
    const float* Wa     = (const float*)d_in[6];
    const float* ba     = (const float*)d_in[7];
    const float* Wv     = (const float*)d_in[8];
    const float* bv     = (const float*)d_in[9];
    const float* Wh     = (const float*)d_in[10];
    const float* bh     = (const float*)d_in[11];
    const float* Wp     = (const float*)d_in[12];
    const float* bp     = (const float*)d_in[13];
    const float* W0h    = (const float*)d_in[14];
    const float* b0h    = (const float*)d_in[15];
    const float* W0c    = (const float*)d_in[16];
    const float* b0c    = (const float*)d_in[17];
    const float* Wo     = (const float*)d_in[18];
    const float* bo     = (const float*)d_in[19];
    const int* ls_rois  = (const int*)d_in[20];
    const int* seq_lens = (const int*)d_in[21];
    float* y = (float*)d_out;

    float *p_mean, *p_h, *p_c, *p_va, *p_pi;
    cudaGetSymbolAddress((void**)&p_mean, g_mean);
    cudaGetSymbolAddress((void**)&p_h,    g_h);
    cudaGetSymbolAddress((void**)&p_c,    g_c);
    cudaGetSymbolAddress((void**)&p_va,   g_va);
    cudaGetSymbolAddress((void**)&p_pi,   g_pi);

    // ---- loop-invariant precompute ----
    mean_vis_kernel<<<B_, 256>>>(visual, ls_rois);
    gemm_nt_bias<<<dim3(H_ / 64, B_ / 64), 256>>>(p_mean, W0h, b0h, p_h, B_, H_, V_);
    gemm_nt_bias<<<dim3(H_ / 64, B_ / 64), 256>>>(p_mean, W0c, b0c, p_c, B_, H_, V_);
    gemm_nt_bias<<<dim3(A_ / 64, (B_ * NROI) / 64), 256>>>(visual, Wv, bv, p_va,
                                                           B_ * NROI, A_, V_);
    gemm_nt_bias<<<dim3((6 * H_) / 64, (B_ * T_) / 64), 256>>>(x, Wi, bi, p_pi,
                                                               B_ * T_, 6 * H_, DIN);

    // ---- recurrent steps: 4 launches/step ----
    const int grid1 = (5 * H_ + A_) / 32;   // 176
    const int grid2 = (5 * H_) / 32;        // 160
    for (int t = 0; t < T_; t++) {
        step1_kernel<<<grid1, 256>>>(Ws, bs, Wh, bh);   // ps + he from h
        attn_kernel<<<B_, 256>>>(visual, Wp, bp, ls_rois);
        step2_kernel<<<grid2, 256>>>(Wa, ba);           // pa from ctx
        gate_kernel<<<B_, 256>>>(Wo, bo, seq_lens, y, t);
    }
}

// round 3
// speedup vs baseline: 1.2381x; 1.1994x over previous
#include <cuda_runtime.h>
#include <math.h>

// Problem dimensions (fixed)
#define B_   128
#define T_   32
#define DIN  1024
#define H_   1024
#define V_   2048
#define A_   512
#define NROI 64

// ---------------- scratch (static device globals; no allocations) ----------
__device__ float g_mean[B_ * V_];                // mean visual     [128,2048]
__device__ float g_h[B_ * H_];                   // hidden state    [128,1024]
__device__ float g_c[B_ * H_];                   // cell state      [128,1024]
__device__ float g_va[(size_t)B_ * NROI * A_];   // visual attn enc [128,64,512]
__device__ float g_pi[(size_t)B_ * T_ * 6 * H_]; // x projections   [128,32,6144]
__device__ float g_he[B_ * A_];                  // h attn enc      [128,512]
__device__ float g_ctx[B_ * V_];                 // context         [128,2048]
__device__ float g_ps[B_ * 5 * H_];              // state proj      [128,5120]
__device__ float g_pa[B_ * 5 * H_];              // attn proj       [128,5120]

__device__ __forceinline__ float sigmoidf(float x) { return 1.0f / (1.0f + expf(-x)); }

// ---------------------------------------------------------------------------
// mean_vis[b,v] = sum_{n<L} visual[b,n,v] / L
// ---------------------------------------------------------------------------
__global__ void mean_vis_kernel(const float* __restrict__ visual,
                                const int* __restrict__ ls_rois)
{
    int b = blockIdx.x;
    int L = ls_rois[b];
    const float4* vb = (const float4*)(visual + (size_t)b * NROI * V_);
    float invL = 1.0f / (float)L;
    float4* out = (float4*)(g_mean + b * V_);
    for (int v4 = threadIdx.x; v4 < V_ / 4; v4 += blockDim.x) {
        float4 s = make_float4(0.f, 0.f, 0.f, 0.f);
#pragma unroll 4
        for (int n = 0; n < NROI; n++) {
            if (n < L) {
                float4 x = vb[(size_t)n * (V_ / 4) + v4];
                s.x += x.x; s.y += x.y; s.z += x.z; s.w += x.w;
            }
        }
        s.x *= invL; s.y *= invL; s.z *= invL; s.w *= invL;
        out[v4] = s;
    }
}

// ---------------------------------------------------------------------------
// Generic NT GEMM with bias (precompute path), register-prefetch pipelined.
// BM=BN=64, BK=16, 256 threads, 4x4 per thread.
// ---------------------------------------------------------------------------
__global__ __launch_bounds__(256)
void gemm_nt_bias(const float* __restrict__ A, const float* __restrict__ W,
                  const float* __restrict__ bias, float* __restrict__ C,
                  int M, int N, int K)
{
    __shared__ float As[16][64];
    __shared__ float Bs[16][64];

    const int bm = blockIdx.y * 64;
    const int bn = blockIdx.x * 64;
    const int tid = threadIdx.x;
    const int tr = tid >> 4;
    const int tc = tid & 15;
    const int lr = tid >> 2;
    const int lc = (tid & 3) << 2;

    const float* Ap = A + (size_t)(bm + lr) * K + lc;
    const float* Wp = W + (size_t)(bn + lr) * K + lc;

    float acc[4][4];
#pragma unroll
    for (int i = 0; i < 4; i++)
#pragma unroll
        for (int j = 0; j < 4; j++) acc[i][j] = 0.0f;

    float4 av = *(const float4*)(Ap);
    float4 wv = *(const float4*)(Wp);

    for (int k0 = 0; k0 < K; k0 += 16) {
        As[lc + 0][lr] = av.x; As[lc + 1][lr] = av.y;
        As[lc + 2][lr] = av.z; As[lc + 3][lr] = av.w;
        Bs[lc + 0][lr] = wv.x; Bs[lc + 1][lr] = wv.y;
        Bs[lc + 2][lr] = wv.z; Bs[lc + 3][lr] = wv.w;
        __syncthreads();
        if (k0 + 16 < K) {
            av = *(const float4*)(Ap + k0 + 16);
            wv = *(const float4*)(Wp + k0 + 16);
        }
#pragma unroll
        for (int kk = 0; kk < 16; kk++) {
            float4 a = *(const float4*)&As[kk][tr << 2];
            float4 w = *(const float4*)&Bs[kk][tc << 2];
            acc[0][0] += a.x * w.x; acc[0][1] += a.x * w.y; acc[0][2] += a.x * w.z; acc[0][3] += a.x * w.w;
            acc[1][0] += a.y * w.x; acc[1][1] += a.y * w.y; acc[1][2] += a.y * w.z; acc[1][3] += a.y * w.w;
            acc[2][0] += a.z * w.x; acc[2][1] += a.z * w.y; acc[2][2] += a.z * w.z; acc[2][3] += a.z * w.w;
            acc[3][0] += a.w * w.x; acc[3][1] += a.w * w.y; acc[3][2] += a.w * w.z; acc[3][3] += a.w * w.w;
        }
        __syncthreads();
    }

    float4 bv4 = *(const float4*)(bias + bn + (tc << 2));
#pragma unroll
    for (int i = 0; i < 4; i++) {
        float4 o;
        o.x = acc[i][0] + bv4.x;
        o.y = acc[i][1] + bv4.y;
        o.z = acc[i][2] + bv4.z;
        o.w = acc[i][3] + bv4.w;
        *(float4*)(C + (size_t)(bm + (tr << 2) + i) * N + bn + (tc << 2)) = o;
    }
}

// ---------------------------------------------------------------------------
// M=128-specialized GEMM core, register-prefetch pipelined.
// One block computes C[0:128, n0:n0+32]; caller offsets W/bias/C to n0.
// BK=16, 256 threads, 4x4 microtile (32 row-groups x 8 col-groups).
// ---------------------------------------------------------------------------
__device__ __forceinline__
void gemm_m128_core(float As[16][128], float Bs[16][32],
                    const float* __restrict__ A, const float* __restrict__ Wn,
                    const float* __restrict__ biasn, float* __restrict__ Cn,
                    int ldc, int K)
{
    const int tid = threadIdx.x;
    const int lm  = tid & 127;            // A-load row
    const int lkh = (tid >> 7) << 3;      // A-load k base: 0 or 8
    const int bn  = tid >> 2;             // W-load row (tid<128 -> 0..31)
    const int bk  = (tid & 3) << 2;       // W-load k base
    const int ty  = tid >> 3;             // 0..31
    const int tx  = tid & 7;              // 0..7

    const float* Ap = A + (size_t)lm * K + lkh;
    const float* Wp = Wn + (size_t)bn * K + bk;

    float acc[4][4];
#pragma unroll
    for (int i = 0; i < 4; i++)
#pragma unroll
        for (int j = 0; j < 4; j++) acc[i][j] = 0.0f;

    float4 a0 = *(const float4*)(Ap);
    float4 a1 = *(const float4*)(Ap + 4);
    float4 w  = make_float4(0.f, 0.f, 0.f, 0.f);
    if (tid < 128) w = *(const float4*)(Wp);

    for (int k0 = 0; k0 < K; k0 += 16) {
        As[lkh + 0][lm] = a0.x; As[lkh + 1][lm] = a0.y;
        As[lkh + 2][lm] = a0.z; As[lkh + 3][lm] = a0.w;
        As[lkh + 4][lm] = a1.x; As[lkh + 5][lm] = a1.y;
        As[lkh + 6][lm] = a1.z; As[lkh + 7][lm] = a1.w;
        if (tid < 128) {
            Bs[bk + 0][bn] = w.x; Bs[bk + 1][bn] = w.y;
            Bs[bk + 2][bn] = w.z; Bs[bk + 3][bn] = w.w;
        }
        __syncthreads();
        if (k0 + 16 < K) {
            a0 = *(const float4*)(Ap + k0 + 16);
            a1 = *(const float4*)(Ap + k0 + 20);
            if (tid < 128) w = *(const float4*)(Wp + k0 + 16);
        }
#pragma unroll
        for (int kk = 0; kk < 16; kk++) {
            float4 a = *(const float4*)&As[kk][ty << 2];
            float4 b = *(const float4*)&Bs[kk][tx << 2];
            acc[0][0] += a.x * b.x; acc[0][1] += a.x * b.y; acc[0][2] += a.x * b.z; acc[0][3] += a.x * b.w;
            acc[1][0] += a.y * b.x; acc[1][1] += a.y * b.y; acc[1][2] += a.y * b.z; acc[1][3] += a.y * b.w;
            acc[2][0] += a.z * b.x; acc[2][1] += a.z * b.y; acc[2][2] += a.z * b.z; acc[2][3] += a.z * b.w;
            acc[3][0] += a.w * b.x; acc[3][1] += a.w * b.y; acc[3][2] += a.w * b.z; acc[3][3] += a.w * b.w;
        }
        __syncthreads();
    }

    float4 bv = *(const float4*)(biasn + (tx << 2));
#pragma unroll
    for (int i = 0; i < 4; i++) {
        float4 o;
        o.x = acc[i][0] + bv.x;
        o.y = acc[i][1] + bv.y;
        o.z = acc[i][2] + bv.z;
        o.w = acc[i][3] + bv.w;
        *(float4*)(Cn + (size_t)((ty << 2) + i) * ldc + (tx << 2)) = o;
    }
}

// step1: [ps | he] = h @ [Ws ; Wh]^T + [bs ; bh].  grid = 176 blocks, occ 2/SM.
__global__ __launch_bounds__(256, 2)
void step1_kernel(const float* __restrict__ Ws, const float* __restrict__ bs,
                  const float* __restrict__ Wh, const float* __restrict__ bh)
{
    __shared__ float As[16][128];
    __shared__ float Bs[16][32];
    int n0 = blockIdx.x << 5;
    if (n0 < 5 * H_) {
        gemm_m128_core(As, Bs, g_h, Ws + (size_t)n0 * H_, bs + n0,
                       g_ps + n0, 5 * H_, H_);
    } else {
        int m = n0 - 5 * H_;
        gemm_m128_core(As, Bs, g_h, Wh + (size_t)m * H_, bh + m,
                       g_he + m, A_, H_);
    }
}

// step2: pa = ctx @ Wa^T + ba.  grid = 160 blocks, occ 2/SM.
__global__ __launch_bounds__(256, 2)
void step2_kernel(const float* __restrict__ Wa, const float* __restrict__ ba)
{
    __shared__ float As[16][128];
    __shared__ float Bs[16][32];
    int n0 = blockIdx.x << 5;
    gemm_m128_core(As, Bs, g_ctx, Wa + (size_t)n0 * V_, ba + n0,
                   g_pa + n0, 5 * H_, V_);
}

// ---------------------------------------------------------------------------
// Attention: logits -> masked softmax -> ctx. One block per batch element.
// ---------------------------------------------------------------------------
__global__ __launch_bounds__(256)
void attn_kernel(const float* __restrict__ visual,
                 const float* __restrict__ Wp, const float* __restrict__ bp,
                 const int* __restrict__ ls_rois)
{
    int b = blockIdx.x;
    int tid = threadIdx.x;
    int warp = tid >> 5, lane = tid & 31;

    __shared__ float he_s[A_];
    __shared__ float wp_s[A_];
    __shared__ float att[NROI];

    // load he and Wp as float4 (A_/4 = 128 vectors)
    if (tid < 128) {
        ((float4*)he_s)[tid] = ((const float4*)(g_he + b * A_))[tid];
        ((float4*)wp_s)[tid] = ((const float4*)Wp)[tid];
    }
    __syncthreads();

    int L = ls_rois[b];

    // logits: warp per n
    for (int n = warp; n < NROI; n += 8) {
        float s = 0.0f;
        if (n < L) {
            const float4* vrow = (const float4*)(g_va + ((size_t)b * NROI + n) * A_);
            const float4* he4 = (const float4*)he_s;
            const float4* wp4 = (const float4*)wp_s;
#pragma unroll
            for (int a4 = lane; a4 < A_ / 4; a4 += 32) {
                float4 v = vrow[a4];
                float4 h = he4[a4];
                float4 p = wp4[a4];
                s += p.x * fmaxf(v.x + h.x, 0.0f);
                s += p.y * fmaxf(v.y + h.y, 0.0f);
                s += p.z * fmaxf(v.z + h.z, 0.0f);
                s += p.w * fmaxf(v.w + h.w, 0.0f);
            }
        }
#pragma unroll
        for (int o = 16; o; o >>= 1) s += __shfl_xor_sync(0xffffffffu, s, o);
        if (lane == 0) att[n] = s + bp[0];
    }
    __syncthreads();

    if (tid == 0) {
        float mx = -3.0e38f;
        for (int n = 0; n < L; n++) mx = fmaxf(mx, att[n]);
        float den = 0.0f;
        for (int n = 0; n < L; n++) { float e = expf(att[n] - mx); att[n] = e; den += e; }
        float inv = 1.0f / den;
        for (int n = 0; n < L; n++) att[n] *= inv;
        for (int n = L; n < NROI; n++) att[n] = 0.0f;
    }
    __syncthreads();

    // ctx: full-64 unrolled (att zero-padded), float4, high MLP
    const float4* vb4 = (const float4*)(visual + (size_t)b * NROI * V_);
    float4* ctx4 = (float4*)(g_ctx + b * V_);
#pragma unroll
    for (int v4 = tid; v4 < V_ / 4; v4 += 256) {
        float4 s = make_float4(0.f, 0.f, 0.f, 0.f);
#pragma unroll 8
        for (int n = 0; n < NROI; n++) {
            float a = att[n];
            float4 x = vb4[(size_t)n * (V_ / 4) + v4];
            s.x += a * x.x; s.y += a * x.y; s.z += a * x.z; s.w += a * x.w;
        }
        ctx4[v4] = s;
    }
}

// ---------------------------------------------------------------------------
// LSTM gates + highway + state update + output projection for step t.
// Fully vectorized: exactly one float4 per thread (H/4 == 256 == blockDim).
// ---------------------------------------------------------------------------
__global__ __launch_bounds__(256)
void gate_kernel(const float* __restrict__ Wo, const float* __restrict__ bo,
                 const int* __restrict__ seq_lens, float* __restrict__ y, int t)
{
    const int HQ = H_ / 4;   // 256
    int b = blockIdx.x;
    int tid = threadIdx.x;
    bool valid = (t < seq_lens[b]);

    const float4* pi = (const float4*)(g_pi + ((size_t)b * T_ + t) * (6 * H_));
    const float4* ps = (const float4*)(g_ps + (size_t)b * (5 * H_));
    const float4* pa = (const float4*)(g_pa + (size_t)b * (5 * H_));
    float4* h4 = (float4*)(g_h + b * H_);
    float4* c4 = (float4*)(g_c + b * H_);

    float4 s0 = pi[0 * HQ + tid], s1 = pi[1 * HQ + tid], s2 = pi[2 * HQ + tid];
    float4 s3 = pi[3 * HQ + tid], s4 = pi[4 * HQ + tid], s5 = pi[5 * HQ + tid];
    float4 q0 = ps[0 * HQ + tid], q1 = ps[1 * HQ + tid], q2 = ps[2 * HQ + tid];
    float4 q3 = ps[3 * HQ + tid], q4 = ps[4 * HQ + tid];
    float4 r0 = pa[0 * HQ + tid], r1 = pa[1 * HQ + tid], r2 = pa[2 * HQ + tid];
    float4 r3 = pa[3 * HQ + tid], r4 = pa[4 * HQ + tid];
    float4 cv = c4[tid];
    float4 wo = ((const float4*)Wo)[tid];

    float out[4], mem[4];
    {
        float pi_[6][4] = {{s0.x,s0.y,s0.z,s0.w},{s1.x,s1.y,s1.z,s1.w},{s2.x,s2.y,s2.z,s2.w},
                           {s3.x,s3.y,s3.z,s3.w},{s4.x,s4.y,s4.z,s4.w},{s5.x,s5.y,s5.z,s5.w}};
        float ps_[5][4] = {{q0.x,q0.y,q0.z,q0.w},{q1.x,q1.y,q1.z,q1.w},{q2.x,q2.y,q2.z,q2.w},
                           {q3.x,q3.y,q3.z,q3.w},{q4.x,q4.y,q4.z,q4.w}};
        float pa_[5][4] = {{r0.x,r0.y,r0.z,r0.w},{r1.x,r1.y,r1.z,r1.w},{r2.x,r2.y,r2.z,r2.w},
                           {r3.x,r3.y,r3.z,r3.w},{r4.x,r4.y,r4.z,r4.w}};
        float cc[4] = {cv.x, cv.y, cv.z, cv.w};
#pragma unroll
        for (int e = 0; e < 4; e++) {
            float ig = sigmoidf(pi_[0][e] + ps_[0][e] + pa_[0][e]);
            float fg = sigmoidf(pi_[1][e] + ps_[1][e] + pa_[1][e]);
            float mi = tanhf   (pi_[2][e] + ps_[2][e] + pa_[2][e]);
            float og = sigmoidf(pi_[3][e] + ps_[3][e] + pa_[3][e]);
            float m  = ig * mi + fg * cc[e];
            float o  = og * tanhf(m);
            float hw = sigmoidf(pi_[4][e] + ps_[4][e] + pa_[4][e]);
            out[e] = hw * o + (1.0f - hw) * pi_[5][e];
            mem[e] = m;
        }
    }

    float part = out[0] * wo.x + out[1] * wo.y + out[2] * wo.z + out[3] * wo.w;

    if (valid) {
        h4[tid] = make_float4(out[0], out[1], out[2], out[3]);
        c4[tid] = make_float4(mem[0], mem[1], mem[2], mem[3]);
    }

    // reduce 256 -> 1
#pragma unroll
    for (int o = 16; o; o >>= 1) part += __shfl_xor_sync(0xffffffffu, part, o);
    __shared__ float red[8];
    if ((tid & 31) == 0) red[tid >> 5] = part;
    __syncthreads();
    if (tid == 0) {
        float s = 0.0f;
#pragma unroll
        for (int w = 0; w < 8; w++) s += red[w];
        y[b * T_ + t] = valid ? (s + bo[0]) : 0.0f;
    }
}

// ---------------------------------------------------------------------------
extern "C" void kernel_launch(void* const* d_in, const int* in_sizes, int n_in,
                              void* d_out, int out_size)
{
    const float* x      = (const float*)d_in[0];
    const float* visual = (const float*)d_in[1];
    const float* Wi     = (const float*)d_in[2];
    const float* bi     = (const float*)d_in[3];
    const float* Ws     = (const float*)d_in[4];
    const float* bs     = (const float*)d_in[5];
    const float* Wa     = (const float*)d_in[6];
    const float* ba     = (const float*)d_in[7];
    const float* Wv     = (const float*)d_in[8];
    const float* bv     = (const float*)d_in[9];
    const float* Wh     = (const float*)d_in[10];
    const float* bh     = (const float*)d_in[11];
    const float* Wp     = (const float*)d_in[12];
    const float* bp     = (const float*)d_in[13];
    const float* W0h    = (const float*)d_in[14];
    const float* b0h    = (const float*)d_in[15];
    const float* W0c    = (const float*)d_in[16];
    const float* b0c    = (const float*)d_in[17];
    const float* Wo     = (const float*)d_in[18];
    const float* bo     = (const float*)d_in[19];
    const int* ls_rois  = (const int*)d_in[20];
    const int* seq_lens = (const int*)d_in[21];
    float* y = (float*)d_out;

    float *p_mean, *p_h, *p_c, *p_va, *p_pi;
    cudaGetSymbolAddress((void**)&p_mean, g_mean);
    cudaGetSymbolAddress((void**)&p_h,    g_h);
    cudaGetSymbolAddress((void**)&p_c,    g_c);
    cudaGetSymbolAddress((void**)&p_va,   g_va);
    cudaGetSymbolAddress((void**)&p_pi,   g_pi);

    // ---- loop-invariant precompute ----
    mean_vis_kernel<<<B_, 256>>>(visual, ls_rois);
    gemm_nt_bias<<<dim3(H_ / 64, B_ / 64), 256>>>(p_mean, W0h, b0h, p_h, B_, H_, V_);
    gemm_nt_bias<<<dim3(H_ / 64, B_ / 64), 256>>>(p_mean, W0c, b0c, p_c, B_, H_, V_);
    gemm_nt_bias<<<dim3(A_ / 64, (B_ * NROI) / 64), 256>>>(visual, Wv, bv, p_va,
                                                           B_ * NROI, A_, V_);
    gemm_nt_bias<<<dim3((6 * H_) / 64, (B_ * T_) / 64), 256>>>(x, Wi, bi, p_pi,
                                                               B_ * T_, 6 * H_, DIN);

    // ---- recurrent steps: 4 launches/step ----
    const int grid1 = (5 * H_ + A_) / 32;   // 176
    const int grid2 = (5 * H_) / 32;        // 160
    for (int t = 0; t < T_; t++) {
        step1_kernel<<<grid1, 256>>>(Ws, bs, Wh, bh);   // ps + he from h
        attn_kernel<<<B_, 256>>>(visual, Wp, bp, ls_rois);
        step2_kernel<<<grid2, 256>>>(Wa, ba);           // pa from ctx
        gate_kernel<<<B_, 256>>>(Wo, bo, seq_lens, y, t);
    }
}